// round 5
// baseline (speedup 1.0000x reference)
#include <cuda_runtime.h>
#include <math.h>

#define LSEQ 262144
#define NMODE 64
#define TCH 32
#define NCHUNK (LSEQ / TCH)         // 8192
#define WPB 8
#define BTH 256
#define GRID_P (NCHUNK / WPB)       // 1024

typedef unsigned long long u64;

// Per-mode constants (double-precision setup)
__device__ float g_zre[NMODE],  g_zim[NMODE];   // z
__device__ float g_z2re[NMODE], g_z2im[NMODE];  // z^2
__device__ float g_z4re[NMODE], g_z4im[NMODE];  // z^4
__device__ float g_cfre[NMODE], g_cfim[NMODE];  // coeff
__device__ float g_wre[NMODE],  g_wim[NMODE];   // w = z^TCH
__device__ float g_w8re[NMODE], g_w8im[NMODE];  // w^8
// Correction table G[m][delta] = cf_m * z_m^(delta+1); Gin = -Im
__device__ __align__(16) float g_Gr[NMODE * TCH];
__device__ __align__(16) float g_Gin[NMODE * TCH];
// Intermediates, [mode][chunk] interleaved complex
__device__ __align__(16) float2 g_P[NMODE * NCHUNK];
__device__ __align__(16) float2 g_C[NMODE * NCHUNK];

// ---- packed f32x2 helpers ----
__device__ __forceinline__ u64 pk2(float lo, float hi) {
    u64 r; asm("mov.b64 %0, {%1,%2};" : "=l"(r) : "f"(lo), "f"(hi)); return r;
}
__device__ __forceinline__ void upk2(u64 v, float& lo, float& hi) {
    asm("mov.b64 {%0,%1}, %2;" : "=f"(lo), "=f"(hi) : "l"(v));
}
__device__ __forceinline__ u64 fma2(u64 a, u64 b, u64 c) {
    u64 d; asm("fma.rn.f32x2 %0, %1, %2, %3;" : "=l"(d) : "l"(a), "l"(b), "l"(c)); return d;
}
__device__ __forceinline__ u64 mul2(u64 a, u64 b) {
    u64 d; asm("mul.rn.f32x2 %0, %1, %2;" : "=l"(d) : "l"(a), "l"(b)); return d;
}

__global__ void setup_kernel(const float* __restrict__ A_re,
                             const float* __restrict__ A_im,
                             const float* __restrict__ C,
                             const float* __restrict__ log_step) {
    int n = threadIdx.x;
    if (n >= NMODE) return;
    double dt  = exp((double)log_step[0]);
    double ar  = (double)A_re[n], ai = (double)A_im[n];
    double dre = dt * ar, dim = dt * ai;
    double e   = exp(dre);
    double zre = e * cos(dim), zim = e * sin(dim);
    double nre = zre - 1.0, nim = zim;
    double inv = 1.0 / (ar * ar + ai * ai);
    double tre = (nre * ar + nim * ai) * inv;
    double tim = (nim * ar - nre * ai) * inv;
    double cr  = (double)C[2 * n], ci = (double)C[2 * n + 1];
    double cfr = cr * tre - ci * tim;
    double cfi = cr * tim + ci * tre;
    g_cfre[n] = (float)cfr;  g_cfim[n] = (float)cfi;
    g_zre[n]  = (float)zre;  g_zim[n]  = (float)zim;
    double e2 = exp(2.0 * dre);
    g_z2re[n] = (float)(e2 * cos(2.0 * dim));
    g_z2im[n] = (float)(e2 * sin(2.0 * dim));
    double e4 = exp(4.0 * dre);
    g_z4re[n] = (float)(e4 * cos(4.0 * dim));
    g_z4im[n] = (float)(e4 * sin(4.0 * dim));
    double ew = exp((double)TCH * dre), wa = (double)TCH * dim;
    g_wre[n]  = (float)(ew * cos(wa));
    g_wim[n]  = (float)(ew * sin(wa));
    double ew8 = exp(8.0 * (double)TCH * dre), wa8 = 8.0 * (double)TCH * dim;
    g_w8re[n]  = (float)(ew8 * cos(wa8));
    g_w8im[n]  = (float)(ew8 * sin(wa8));
    // G table: cf * z^(delta+1), Gin pre-negated
    double gr = cfr, gi = cfi;
    for (int d = 0; d < TCH; d++) {
        double ngr = gr * zre - gi * zim;
        double ngi = gr * zim + gi * zre;
        gr = ngr; gi = ngi;
        g_Gr[n * TCH + d]  = (float)gr;
        g_Gin[n * TCH + d] = (float)(-gi);
    }
}

// Phase 1: zero-init recurrence (4-step unrolled), emits y_local AND partials.
__global__ __launch_bounds__(BTH) void local_kernel(const float* __restrict__ u,
                                                    const float* __restrict__ D,
                                                    float* __restrict__ y) {
    __shared__ __align__(16) float su[WPB * TCH];
    __shared__ __align__(16) float2 sP[NMODE][WPB];
    __shared__ __align__(16) float red[WPB][32 * 36];
    int tid  = threadIdx.x;
    int base = blockIdx.x * (WPB * TCH);
    su[tid] = u[base + tid];
    __syncthreads();

    int warp = tid >> 5, lane = tid & 31;
    u64 zr  = pk2(g_zre[lane],  g_zre[lane + 32]);
    float c0_ = g_zim[lane], c1_ = g_zim[lane + 32];
    u64 zi  = pk2(c0_, c1_), nzi = pk2(-c0_, -c1_);
    u64 z2r = pk2(g_z2re[lane], g_z2re[lane + 32]);
    float a0 = g_z2im[lane], a1 = g_z2im[lane + 32];
    u64 z2i = pk2(a0, a1), nz2i = pk2(-a0, -a1);
    u64 fr  = pk2(g_cfre[lane], g_cfre[lane + 32]);
    float fi0 = g_cfim[lane], fi1 = g_cfim[lane + 32];
    u64 nfi = pk2(-fi0, -fi1);
    u64 sr = pk2(0.f, 0.f), si = sr;
    const float4* uw = (const float4*)&su[warp * TCH];
    float* rw = &red[warp][0];

#pragma unroll
    for (int i = 0; i < TCH / 4; i++) {
        float4 uu = uw[i];
        u64 u1p = pk2(uu.x, uu.x), u2p = pk2(uu.y, uu.y);
        u64 u3p = pk2(uu.z, uu.z), u4p = pk2(uu.w, uu.w);
        u64 t1r = fma2(zr, u1p, u2p), t1i = mul2(zi, u1p);
        u64 t2r = fma2(zr, u3p, u4p), t2i = mul2(zi, u3p);
        u64 s1r = fma2(zr, sr, fma2(nzi, si, u1p));
        u64 s1i = fma2(zi, sr, mul2(zr, si));
        u64 s2r = fma2(z2r, sr, fma2(nz2i, si, t1r));
        u64 s2i = fma2(z2i, sr, fma2(z2r, si, t1i));
        u64 s3r = fma2(zr, s2r, fma2(nzi, s2i, u3p));
        u64 s3i = fma2(zi, s2r, mul2(zr, s2i));
        u64 s4r = fma2(z2r, s2r, fma2(nz2i, s2i, t2r));
        u64 s4i = fma2(z2i, s2r, fma2(z2r, s2i, t2i));
        sr = s4r; si = s4i;
        u64 cp1 = fma2(fr, s1r, mul2(nfi, s1i));
        u64 cp2 = fma2(fr, s2r, mul2(nfi, s2i));
        u64 cp3 = fma2(fr, s3r, mul2(nfi, s3i));
        u64 cp4 = fma2(fr, s4r, mul2(nfi, s4i));
        float x0, x1, y0, y1, w0, w1, v0, v1;
        upk2(cp1, x0, x1); upk2(cp2, y0, y1);
        upk2(cp3, w0, w1); upk2(cp4, v0, v1);
        *(float4*)&rw[lane * 36 + 4 * i] =
            make_float4(x0 + x1, y0 + y1, w0 + w1, v0 + v1);
    }
    __syncwarp();
    // 4 interleaved accumulator chains (depth 8 each, not 32)
    float b0 = 0.f, b1 = 0.f, b2 = 0.f, b3 = 0.f;
#pragma unroll
    for (int l = 0; l < 32; l += 4) {
        b0 += rw[(l + 0) * 36 + lane];
        b1 += rw[(l + 1) * 36 + lane];
        b2 += rw[(l + 2) * 36 + lane];
        b3 += rw[(l + 3) * 36 + lane];
    }
    float uv = su[warp * TCH + lane];
    y[base + warp * TCH + lane] = fmaf(D[0], uv, (b0 + b1) + (b2 + b3));
    // partials
    float s0r_, s1r_, s0i_, s1i_;
    upk2(sr, s0r_, s1r_); upk2(si, s0i_, s1i_);
    sP[lane][warp]      = make_float2(s0r_, s0i_);
    sP[lane + 32][warp] = make_float2(s1r_, s1i_);
    __syncthreads();
    int row = tid >> 2, col = (tid & 3) * 2;
    int cc0 = blockIdx.x * WPB;
    *(float4*)&g_P[row * NCHUNK + cc0 + col] = *(const float4*)&sP[row][col];
}

// Phase 2: per-mode scan over 8192 partials; fold 8 (Horner w), scan W=w^8.
__global__ __launch_bounds__(1024) void scan_kernel() {
    __shared__ float sre[1024], sim_[1024];
    int mode = blockIdx.x, t = threadIdx.x;
    float wr = g_wre[mode], wi = g_wim[mode];
    const float2* P = &g_P[mode * NCHUNK];
    float2 p[8];
#pragma unroll
    for (int q = 0; q < 4; q++) {
        float4 a = *(const float4*)&P[8 * t + 2 * q];
        p[2 * q]     = make_float2(a.x, a.y);
        p[2 * q + 1] = make_float2(a.z, a.w);
    }
    float vr = p[0].x, vi = p[0].y;
#pragma unroll
    for (int j = 1; j < 8; j++) {
        float nr = fmaf(wr, vr, fmaf(-wi, vi, p[j].x));
        float ni = fmaf(wi, vr, fmaf( wr, vi, p[j].y));
        vr = nr; vi = ni;
    }
    sre[t] = vr; sim_[t] = vi;
    float cwr = g_w8re[mode], cwi = g_w8im[mode];
    __syncthreads();
    for (int k = 1; k < 1024; k <<= 1) {
        float ore = 0.f, oim = 0.f;
        if (t >= k) { ore = sre[t - k]; oim = sim_[t - k]; }
        __syncthreads();
        vr += cwr * ore - cwi * oim;
        vi += cwr * oim + cwi * ore;
        sre[t] = vr; sim_[t] = vi;
        float nwr = cwr * cwr - cwi * cwi;
        cwi = 2.f * cwr * cwi; cwr = nwr;
        __syncthreads();
    }
    // exclusive carries for chunks 8t..8t+7
    float er = 0.f, ei = 0.f;
    if (t > 0) { er = sre[t - 1]; ei = sim_[t - 1]; }
    float2 e[8];
    e[0] = make_float2(er, ei);
#pragma unroll
    for (int j = 1; j < 8; j++) {
        float nr = fmaf(wr, er, fmaf(-wi, ei, p[j - 1].x));
        float ni = fmaf(wi, er, fmaf( wr, ei, p[j - 1].y));
        er = nr; ei = ni;
        e[j] = make_float2(er, ei);
    }
    float2* Cp = &g_C[mode * NCHUNK + 8 * t];
#pragma unroll
    for (int q = 0; q < 4; q++)
        *(float4*)&Cp[2 * q] = make_float4(e[2 * q].x, e[2 * q].y,
                                           e[2 * q + 1].x, e[2 * q + 1].y);
}

// Phase 3: y += G x carry. Warp = 32 chunks (lane=chunk) x 16-delta half.
#define CORRB 128
__global__ __launch_bounds__(CORRB) void corr_kernel(float* __restrict__ y) {
    __shared__ __align__(16) float sGr[NMODE * TCH], sGin[NMODE * TCH];
    int tid = threadIdx.x;
    for (int i = tid; i < NMODE * TCH; i += CORRB) {
        sGr[i] = g_Gr[i]; sGin[i] = g_Gin[i];
    }
    __syncthreads();
    int warp = tid >> 5, lane = tid & 31;
    int group = blockIdx.x * 2 + (warp >> 1);    // 32-chunk group
    int d0 = (warp & 1) * 16;
    int c0 = group * 32;
    u64 acc[8];
#pragma unroll
    for (int j = 0; j < 8; j++) acc[j] = pk2(0.f, 0.f);
#pragma unroll 4
    for (int m = 0; m < NMODE; m++) {
        float2 cc = g_C[m * NCHUNK + c0 + lane];    // coalesced LDG.64
        u64 cr2 = pk2(cc.x, cc.x), ci2 = pk2(cc.y, cc.y);
        const float* Gr = &sGr[m * TCH + d0];
        const float* Gi = &sGin[m * TCH + d0];
#pragma unroll
        for (int j = 0; j < 8; j++) {
            u64 gr = *(const u64*)&Gr[2 * j];       // broadcast LDS.64
            u64 gi = *(const u64*)&Gi[2 * j];
            acc[j] = fma2(gr, cr2, acc[j]);
            acc[j] = fma2(gi, ci2, acc[j]);
        }
    }
    float4* yp = (float4*)&y[(c0 + lane) * TCH + d0];
#pragma unroll
    for (int q = 0; q < 4; q++) {
        float4 v = yp[q];
        float lo, hi;
        upk2(acc[2 * q], lo, hi);     v.x += lo; v.y += hi;
        upk2(acc[2 * q + 1], lo, hi); v.z += lo; v.w += hi;
        yp[q] = v;
    }
}

extern "C" void kernel_launch(void* const* d_in, const int* in_sizes, int n_in,
                              void* d_out, int out_size) {
    const float* u        = (const float*)d_in[0];
    const float* A_re     = (const float*)d_in[1];
    const float* A_im     = (const float*)d_in[2];
    const float* C        = (const float*)d_in[3];
    const float* D        = (const float*)d_in[4];
    const float* log_step = (const float*)d_in[5];
    float* y = (float*)d_out;

    setup_kernel<<<1, NMODE>>>(A_re, A_im, C, log_step);
    local_kernel<<<GRID_P, BTH>>>(u, D, y);
    scan_kernel<<<NMODE, 1024>>>();
    corr_kernel<<<NCHUNK / 64, CORRB>>>(y);
}

// round 6
// speedup vs baseline: 1.7172x; 1.7172x over previous
#include <cuda_runtime.h>
#include <math.h>

#define LSEQ 262144
#define NMODE 64
#define TCH 64
#define NCHUNK (LSEQ / TCH)     // 4096
#define WPB 8
#define BTH 256
#define GRID_P (NCHUNK / WPB)   // 512

#define CB_CH 16                // chunks per ygemm block
#define YG_TH 256
#define GRID_Y (NCHUNK / CB_CH) // 256

typedef unsigned long long u64;

// Per-mode constants
__device__ float g_zre[NMODE],  g_zim[NMODE];
__device__ float g_z2re[NMODE], g_z2im[NMODE];
__device__ float g_z4re[NMODE], g_z4im[NMODE];
__device__ float g_wre[NMODE],  g_wim[NMODE];   // w = z^TCH
__device__ float g_w4re[NMODE], g_w4im[NMODE];  // w^4
// G[m][d] = cf*z^(d+1): Gr = Re, Gin = -Im
__device__ __align__(16) float g_Gr[NMODE * TCH], g_Gin[NMODE * TCH];
// padded splat table: g_ktab[t] = (Ktil[t-64], Ktil[t-63]), 0 outside [0,63]
__device__ __align__(16) u64 g_ktab[128];
// intermediates [mode][chunk]
__device__ __align__(16) float2 g_P[NMODE * NCHUNK];
__device__ __align__(16) float2 g_C[NMODE * NCHUNK];

// ---- packed f32x2 helpers ----
__device__ __forceinline__ u64 pk2(float lo, float hi) {
    u64 r; asm("mov.b64 %0, {%1,%2};" : "=l"(r) : "f"(lo), "f"(hi)); return r;
}
__device__ __forceinline__ void upk2(u64 v, float& lo, float& hi) {
    asm("mov.b64 {%0,%1}, %2;" : "=f"(lo), "=f"(hi) : "l"(v));
}
__device__ __forceinline__ u64 fma2(u64 a, u64 b, u64 c) {
    u64 d; asm("fma.rn.f32x2 %0, %1, %2, %3;" : "=l"(d) : "l"(a), "l"(b), "l"(c)); return d;
}
__device__ __forceinline__ u64 mul2(u64 a, u64 b) {
    u64 d; asm("mul.rn.f32x2 %0, %1, %2;" : "=l"(d) : "l"(a), "l"(b)); return d;
}

// Float-only setup (no FP64): constants, G table, Ktilde + padded pair table.
__global__ void setup_kernel(const float* __restrict__ A_re,
                             const float* __restrict__ A_im,
                             const float* __restrict__ C,
                             const float* __restrict__ log_step) {
    __shared__ float sGre[NMODE * TCH];
    __shared__ float sCfr[NMODE];
    __shared__ float sKt[TCH];
    int n = threadIdx.x;   // 64 threads
    float dt  = expf(log_step[0]);
    float ar  = A_re[n], ai = A_im[n];
    float dre = dt * ar, dim = dt * ai;
    float em  = expf(dre);
    float zr  = em * cosf(dim), zi = em * sinf(dim);
    // cf = Ct*(z-1)/A
    float nr = zr - 1.f, ni = zi;
    float inv = 1.f / (ar * ar + ai * ai);
    float tre = (nr * ar + ni * ai) * inv;
    float tim = (ni * ar - nr * ai) * inv;
    float cr = C[2 * n], ci = C[2 * n + 1];
    float cfr = cr * tre - ci * tim;
    float cfi = cr * tim + ci * tre;
    g_zre[n] = zr; g_zim[n] = zi;
    float p2r = zr * zr - zi * zi,    p2i = 2.f * zr * zi;
    g_z2re[n] = p2r; g_z2im[n] = p2i;
    float p4r = p2r * p2r - p2i * p2i, p4i = 2.f * p2r * p2i;
    g_z4re[n] = p4r; g_z4im[n] = p4i;
    float p8r  = p4r * p4r - p4i * p4i,     p8i  = 2.f * p4r * p4i;
    float p16r = p8r * p8r - p8i * p8i,     p16i = 2.f * p8r * p8i;
    float p32r = p16r * p16r - p16i * p16i, p32i = 2.f * p16r * p16i;
    float wr   = p32r * p32r - p32i * p32i, wi   = 2.f * p32r * p32i; // z^64
    g_wre[n] = wr; g_wim[n] = wi;
    float w2r = wr * wr - wi * wi,     w2i = 2.f * wr * wi;
    float w4r = w2r * w2r - w2i * w2i, w4i = 2.f * w2r * w2i;
    g_w4re[n] = w4r; g_w4im[n] = w4i;
    // G table: cf*z^(d+1)
    float gr = cfr, gi = cfi;
    for (int d = 0; d < TCH; d++) {
        float t1 = gr * zr - gi * zi;
        gi = gr * zi + gi * zr; gr = t1;
        g_Gr[n * TCH + d]  = gr;
        g_Gin[n * TCH + d] = -gi;
        sGre[n * TCH + d]  = gr;
    }
    sCfr[n] = cfr;
    __syncthreads();
    // Ktilde[d] = sum_m Re(cf*z^d): d=0 -> sum cfr; d>0 -> sum Gr[m][d-1]
    float acc = 0.f;
    if (n == 0) { for (int m = 0; m < NMODE; m++) acc += sCfr[m]; }
    else        { for (int m = 0; m < NMODE; m++) acc += sGre[m * TCH + n - 1]; }
    sKt[n] = acc;
    __syncthreads();
    for (int t = n; t < 128; t += 64) {
        int li = t - 64, hi = t - 63;
        float lo = (li >= 0 && li < TCH) ? sKt[li] : 0.f;
        float hh = (hi >= 0 && hi < TCH) ? sKt[hi] : 0.f;
        g_ktab[t] = pk2(lo, hh);
    }
}

// Phase 1: per-chunk recurrence partials (4-step unrolled), coalesced stores.
__global__ __launch_bounds__(BTH) void partial_kernel(const float* __restrict__ u) {
    __shared__ __align__(16) float su[WPB * TCH];
    __shared__ __align__(16) float2 sP[NMODE][WPB];
    int tid  = threadIdx.x;
    int base = blockIdx.x * (WPB * TCH);
    ((float2*)su)[tid] = ((const float2*)(u + base))[tid];
    __syncthreads();

    int warp = tid >> 5, lane = tid & 31;
    u64 zr  = pk2(g_zre[lane],  g_zre[lane + 32]);
    u64 zi  = pk2(g_zim[lane],  g_zim[lane + 32]);
    u64 z2r = pk2(g_z2re[lane], g_z2re[lane + 32]);
    float a0 = g_z2im[lane], a1 = g_z2im[lane + 32];
    u64 z2i = pk2(a0, a1), nz2i = pk2(-a0, -a1);
    u64 z4r = pk2(g_z4re[lane], g_z4re[lane + 32]);
    float b0 = g_z4im[lane], b1 = g_z4im[lane + 32];
    u64 z4i = pk2(b0, b1), nz4i = pk2(-b0, -b1);
    u64 sr = 0, si = 0;
    const float4* uw = (const float4*)&su[warp * TCH];
#pragma unroll
    for (int i = 0; i < TCH / 4; i++) {
        float4 uu = uw[i];
        u64 u1p = pk2(uu.x, uu.x), u2p = pk2(uu.y, uu.y);
        u64 u3p = pk2(uu.z, uu.z), u4p = pk2(uu.w, uu.w);
        u64 t1r = fma2(zr, u1p, u2p), t1i = mul2(zi, u1p);
        u64 t2r = fma2(zr, u3p, u4p), t2i = mul2(zi, u3p);
        u64 br = fma2(z2r, t1r, fma2(nz2i, t1i, t2r));
        u64 bi = fma2(z2i, t1r, fma2(z2r, t1i, t2i));
        u64 nr = fma2(z4r, sr, fma2(nz4i, si, br));
        u64 ni = fma2(z4i, sr, fma2(z4r, si, bi));
        sr = nr; si = ni;
    }
    float s0r, s1r, s0i, s1i;
    upk2(sr, s0r, s1r); upk2(si, s0i, s1i);
    sP[lane][warp]      = make_float2(s0r, s0i);
    sP[lane + 32][warp] = make_float2(s1r, s1i);
    __syncthreads();
    int row = tid >> 2, col = (tid & 3) * 2;
    int c0  = blockIdx.x * WPB;
    *(float4*)&g_P[row * NCHUNK + c0 + col] = *(const float4*)&sP[row][col];
}

// Phase 2: per-mode scan over 4096 partials; fold 4 (Horner w), scan W=w^4.
__global__ __launch_bounds__(1024) void scan_kernel() {
    __shared__ float sre[1024], sim_[1024];
    int mode = blockIdx.x, t = threadIdx.x;
    float wr = g_wre[mode], wi = g_wim[mode];
    const float2* P = &g_P[mode * NCHUNK];
    float4 pa = *(const float4*)&P[4 * t];
    float4 pb = *(const float4*)&P[4 * t + 2];
    float p0r = pa.x, p0i = pa.y, p1r = pa.z, p1i = pa.w;
    float p2r = pb.x, p2i = pb.y, p3r = pb.z, p3i = pb.w;
    float vr = p0r, vi = p0i, nr, ni;
    nr = fmaf(wr, vr, fmaf(-wi, vi, p1r));
    ni = fmaf(wi, vr, fmaf( wr, vi, p1i)); vr = nr; vi = ni;
    nr = fmaf(wr, vr, fmaf(-wi, vi, p2r));
    ni = fmaf(wi, vr, fmaf( wr, vi, p2i)); vr = nr; vi = ni;
    nr = fmaf(wr, vr, fmaf(-wi, vi, p3r));
    ni = fmaf(wi, vr, fmaf( wr, vi, p3i)); vr = nr; vi = ni;
    sre[t] = vr; sim_[t] = vi;
    float cwr = g_w4re[mode], cwi = g_w4im[mode];
    __syncthreads();
    for (int k = 1; k < 1024; k <<= 1) {
        float ore = 0.f, oim = 0.f;
        if (t >= k) { ore = sre[t - k]; oim = sim_[t - k]; }
        __syncthreads();
        vr += cwr * ore - cwi * oim;
        vi += cwr * oim + cwi * ore;
        sre[t] = vr; sim_[t] = vi;
        float nwr = cwr * cwr - cwi * cwi;
        cwi = 2.f * cwr * cwi; cwr = nwr;
        __syncthreads();
    }
    float e0r = 0.f, e0i = 0.f;
    if (t > 0) { e0r = sre[t - 1]; e0i = sim_[t - 1]; }
    float e1r = fmaf(wr, e0r, fmaf(-wi, e0i, p0r));
    float e1i = fmaf(wi, e0r, fmaf( wr, e0i, p0i));
    float e2r = fmaf(wr, e1r, fmaf(-wi, e1i, p1r));
    float e2i = fmaf(wi, e1r, fmaf( wr, e1i, p1i));
    float e3r = fmaf(wr, e2r, fmaf(-wi, e2i, p2r));
    float e3i = fmaf(wi, e2r, fmaf( wr, e2i, p2i));
    float2* Cp = &g_C[mode * NCHUNK + 4 * t];
    *(float4*)&Cp[0] = make_float4(e0r, e0i, e1r, e1i);
    *(float4*)&Cp[2] = make_float4(e2r, e2i, e3r, e3i);
}

// Phase 3 (fused output): y = D*u + triangular-Toeplitz(Ktil) x u + G x carry.
// Thread = (chunk, 4 deltas as 2 f32x2 pairs). Chain-free dense contraction.
__global__ __launch_bounds__(YG_TH) void ygemm_kernel(const float* __restrict__ u,
                                                      const float* __restrict__ D,
                                                      float* __restrict__ y) {
    extern __shared__ __align__(16) char smem[];
    u64*  sU2  = (u64*)smem;                 // [16][65] splatted u
    u64*  sCr2 = sU2 + 16 * 65;              // [64][16] splatted carry re
    u64*  sCi2 = sCr2 + 64 * 16;             // [64][16] splatted carry im
    u64*  sK   = sCi2 + 64 * 16;             // [128] padded Ktil pairs
    float* sGr  = (float*)(sK + 128);        // [64*64]
    float* sGin = sGr + NMODE * TCH;         // [64*64]

    int tid = threadIdx.x;
    int c0  = blockIdx.x * CB_CH;
    int ubase = c0 * TCH;
    for (int i = tid; i < CB_CH * TCH; i += YG_TH) {
        float v = u[ubase + i];
        sU2[(i >> 6) * 65 + (i & 63)] = pk2(v, v);
    }
    for (int i = tid; i < NMODE * CB_CH; i += YG_TH) {
        int m = i >> 4, c = i & 15;
        float2 v = g_C[m * NCHUNK + c0 + c];
        sCr2[m * 16 + c] = pk2(v.x, v.x);
        sCi2[m * 16 + c] = pk2(v.y, v.y);
    }
    for (int i = tid; i < NMODE * TCH; i += YG_TH) {
        sGr[i] = g_Gr[i]; sGin[i] = g_Gin[i];
    }
    if (tid < 128) sK[tid] = g_ktab[tid];
    __syncthreads();

    int cl = tid & 15, dg = tid >> 4;
    int d0 = dg * 4;
    u64 a0 = 0, a1 = 0;   // delta pairs (d0,d0+1), (d0+2,d0+3)
    const u64* urow = &sU2[cl * 65];
    const u64* kb   = &sK[64 + d0];
#pragma unroll 8
    for (int j = 0; j < TCH; j++) {
        u64 uj = urow[j];
        a0 = fma2(kb[0 - j], uj, a0);
        a1 = fma2(kb[2 - j], uj, a1);
    }
#pragma unroll 8
    for (int m = 0; m < NMODE; m++) {
        u64 cr2 = sCr2[m * 16 + cl];
        u64 ci2 = sCi2[m * 16 + cl];
        const u64* gr = (const u64*)&sGr[m * TCH + d0];
        const u64* gi = (const u64*)&sGin[m * TCH + d0];
        a0 = fma2(gr[0], cr2, a0);
        a0 = fma2(gi[0], ci2, a0);
        a1 = fma2(gr[1], cr2, a1);
        a1 = fma2(gi[1], ci2, a1);
    }
    int gc = c0 + cl;
    float4 uv = *(const float4*)&u[gc * TCH + d0];
    float Dv = D[0];
    float o0, o1, o2, o3;
    upk2(a0, o0, o1); upk2(a1, o2, o3);
    float4 outv = make_float4(fmaf(Dv, uv.x, o0), fmaf(Dv, uv.y, o1),
                              fmaf(Dv, uv.z, o2), fmaf(Dv, uv.w, o3));
    *(float4*)&y[gc * TCH + d0] = outv;
}

#define YG_SMEM ((16 * 65 + 64 * 16 + 64 * 16 + 128) * 8 + NMODE * TCH * 2 * 4)

extern "C" void kernel_launch(void* const* d_in, const int* in_sizes, int n_in,
                              void* d_out, int out_size) {
    const float* u        = (const float*)d_in[0];
    const float* A_re     = (const float*)d_in[1];
    const float* A_im     = (const float*)d_in[2];
    const float* C        = (const float*)d_in[3];
    const float* D        = (const float*)d_in[4];
    const float* log_step = (const float*)d_in[5];
    float* y = (float*)d_out;

    cudaFuncSetAttribute(ygemm_kernel,
                         cudaFuncAttributeMaxDynamicSharedMemorySize, YG_SMEM);

    setup_kernel<<<1, NMODE>>>(A_re, A_im, C, log_step);
    partial_kernel<<<GRID_P, BTH>>>(u);
    scan_kernel<<<NMODE, 1024>>>();
    ygemm_kernel<<<GRID_Y, YG_TH, YG_SMEM>>>(u, D, y);
}